// round 6
// baseline (speedup 1.0000x reference)
#include <cuda_runtime.h>
#include <math.h>

#define NB    16
#define NP    32768
#define NC    81
#define CM1   80
#define NBINS 2048
#define SCAP  4096
#define GRCAP 128
#define NCAND 400
#define NOUT  100
#define NTHR  1024

// ---------------- scratch (static device globals; zero-initialized at load) --------
__device__ float              g_rowsc[NB * NP];
__device__ unsigned int       g_hist[NB * NBINS];   // k_thresh re-zeroes after use
__device__ int                g_btm[NB];            // row filter bin (bt-6)
__device__ int                g_bte[NB];            // element filter bin (bt-4)
__device__ int                g_cnt[NB];
__device__ unsigned long long g_cand[NB * SCAP];

__device__ __forceinline__ int binf(float s) {
    int b = (int)floorf((s + 30.0f) * (NBINS / 40.0f));
    b = b < 0 ? 0 : b;
    b = b > (NBINS - 1) ? (NBINS - 1) : b;
    return b;
}

__device__ __forceinline__ unsigned int okey(float s) {
    unsigned int u = __float_as_uint(s);
    return (u & 0x80000000u) ? ~u : (u | 0x80000000u);
}
__device__ __forceinline__ float unokey(unsigned int k) {
    return __uint_as_float((k & 0x80000000u) ? (k ^ 0x80000000u) : ~k);
}

// Schraudolph fast exp: 1 FFMA + 1 F2I; max rel err ~ +-3% (log err <= 0.031).
__device__ __forceinline__ float fexp(float x) {
    return __int_as_float((int)(12102203.0f * x + 1064986816.0f));
}

// ---------------- K1: approx row-score + histogram (cheap exp, REDUX max) ----------
__global__ void k_lse_hist(const float* __restrict__ logits, int img0) {
    const int img = img0 + blockIdx.y;
    const int lane = threadIdx.x & 31;
    const int gw = (blockIdx.x * blockDim.x + threadIdx.x) >> 5;
    const int nw = (gridDim.x * blockDim.x) >> 5;   // 4096 warps/image
    const float* base = logits + (size_t)img * NP * NC;

    for (int p0 = gw; p0 < NP; p0 += 2 * nw) {
        int p1 = p0 + nw;   // NP == 8*nw, always in range
        const float* r0 = base + (size_t)p0 * NC;
        const float* r1 = base + (size_t)p1 * NC;
        float a0 = r0[lane], b0 = r0[lane + 32];
        float a1 = r1[lane], b1 = r1[lane + 32];
        bool t3 = (lane < 17);
        float c0 = t3 ? r0[lane + 64] : -1e30f;
        float c1 = t3 ? r1[lane + 64] : -1e30f;
        float fa0 = (lane == 0) ? -1e30f : a0;   // exclude background from fg-max
        float fa1 = (lane == 0) ? -1e30f : a1;
        float fg0 = fmaxf(fmaxf(fa0, b0), c0);
        float fg1 = fmaxf(fmaxf(fa1, b1), c1);
        unsigned int m0 = __reduce_max_sync(0xffffffffu, okey(fg0));
        unsigned int m1 = __reduce_max_sync(0xffffffffu, okey(fg1));
        float s0 = fexp(a0) + fexp(b0) + (t3 ? fexp(c0) : 0.0f);
        float s1 = fexp(a1) + fexp(b1) + (t3 ? fexp(c1) : 0.0f);
#pragma unroll
        for (int o = 16; o; o >>= 1) {
            s0 += __shfl_xor_sync(0xffffffffu, s0, o);
            s1 += __shfl_xor_sync(0xffffffffu, s1, o);
        }
        if (lane == 0) {
            float rs0 = unokey(m0) - __logf(s0);
            float rs1 = unokey(m1) - __logf(s1);
            g_rowsc[img * NP + p0] = rs0;
            g_rowsc[img * NP + p1] = rs1;
            atomicAdd(&g_hist[img * NBINS + binf(rs0)], 1u);
            atomicAdd(&g_hist[img * NBINS + binf(rs1)], 1u);
        }
    }
}

// ---------------- K2: threshold find + hist re-zero + counter reset ----------------
__global__ void __launch_bounds__(NTHR, 1) k_thresh() {
    __shared__ unsigned int scan[32];
    __shared__ int sbt;
    const int img = blockIdx.x;
    const int tid = threadIdx.x;
    const int lane = tid & 31;
    const int warp = tid >> 5;

    const int hi = NBINS - 1 - 2 * tid;
    unsigned int v0 = g_hist[img * NBINS + hi];
    unsigned int v1 = g_hist[img * NBINS + hi - 1];
    unsigned int s = v0 + v1;
    unsigned int x = s;
#pragma unroll
    for (int o = 1; o < 32; o <<= 1) {
        unsigned int y = __shfl_up_sync(0xffffffffu, x, o);
        if (lane >= o) x += y;
    }
    if (lane == 31) scan[warp] = x;
    __syncthreads();
    if (warp == 0) {
        unsigned int t = scan[lane];
        unsigned int tx = t;
#pragma unroll
        for (int o = 1; o < 32; o <<= 1) {
            unsigned int y = __shfl_up_sync(0xffffffffu, tx, o);
            if (lane >= o) tx += y;
        }
        scan[lane] = tx - t;   // exclusive warp offsets
    }
    __syncthreads();
    {
        unsigned int incl = x + scan[warp];
        unsigned int excl = incl - s;
        if (excl < NCAND && incl >= NCAND)
            sbt = (excl + v0 >= NCAND) ? hi : hi - 1;
        if (tid == NTHR - 1 && incl < NCAND) sbt = 0;   // never expected
    }
    g_hist[img * NBINS + hi] = 0u;
    g_hist[img * NBINS + hi - 1] = 0u;
    __syncthreads();
    if (tid == 0) {
        int bt = sbt;
        int btm = bt - 6; if (btm < 0) btm = 0;   // row margin: covers 2x approx err
        int bte = bt - 4; if (bte < 0) bte = 0;   // element margin: covers 1x approx err
        g_btm[img] = btm;
        g_bte[img] = bte;
        g_cnt[img] = 0;
    }
}

// ---------------- K3: gather rows + EXACT rescore + push candidates ----------------
__global__ void k_gather(const float* __restrict__ logits) {
    __shared__ int rows[GRCAP];
    __shared__ int nr;
    const int img = blockIdx.y;
    const int tid = threadIdx.x;
    const int lane = tid & 31;
    const int warp = tid >> 5;
    const int btm = g_btm[img];
    const int bte = g_bte[img];

    if (tid == 0) nr = 0;
    __syncthreads();

    // this block scans 512 rows = 128 float4 of approx scores
    const int pbase = blockIdx.x * 512;
    const float4* rsc4 = (const float4*)(g_rowsc + (size_t)img * NP + pbase);
    {
        float4 v = rsc4[tid];
        int br = pbase + tid * 4;
        if (binf(v.x) >= btm) { int q = atomicAdd(&nr, 1); if (q < GRCAP) rows[q] = br; }
        if (binf(v.y) >= btm) { int q = atomicAdd(&nr, 1); if (q < GRCAP) rows[q] = br + 1; }
        if (binf(v.z) >= btm) { int q = atomicAdd(&nr, 1); if (q < GRCAP) rows[q] = br + 2; }
        if (binf(v.w) >= btm) { int q = atomicAdd(&nr, 1); if (q < GRCAP) rows[q] = br + 3; }
    }
    __syncthreads();

    int n = nr < GRCAP ? nr : GRCAP;
    for (int ri = warp; ri < n; ri += 4) {
        int p = rows[ri];
        const float* row = logits + ((size_t)img * NP + p) * NC;
        float a = row[lane];
        float b = row[lane + 32];
        float c = (lane < 17) ? row[lane + 64] : -INFINITY;
        float m = fmaxf(fmaxf(a, b), c);
#pragma unroll
        for (int o = 16; o; o >>= 1) m = fmaxf(m, __shfl_xor_sync(0xffffffffu, m, o));
        float sv = expf(a - m) + expf(b - m);
        if (lane < 17) sv += expf(c - m);
#pragma unroll
        for (int o = 16; o; o >>= 1) sv += __shfl_xor_sync(0xffffffffu, sv, o);
        float logs = logf(sv);
#pragma unroll
        for (int k = 0; k < 3; k++) {
            int cc = lane + 32 * k;
            float xv = (k == 0) ? a : (k == 1) ? b : c;
            if (cc >= 1 && cc < NC) {
                float scv = (xv - m) - logs;
                if (binf(scv) >= bte) {
                    int pos = atomicAdd(&g_cnt[img], 1);
                    if (pos < SCAP) {
                        unsigned int flat = (unsigned int)(p * CM1 + (cc - 1));
                        g_cand[img * SCAP + pos] =
                            ((unsigned long long)okey(scv) << 32) | (unsigned int)(~flat);
                    }
                }
            }
        }
    }
}

// ---------------- K4: sort + decode + bitmask NMS + output ----------------
struct SmemFinal {
    unsigned long long cand[SCAP];     // 32 KB
    float4 obx4[NCAND];
    float bx[NCAND][4];
    float sc[NCAND];
    int   lb[NCAND];
    float area[NCAND];
    unsigned int adj[NCAND][13];
    unsigned int keepw[13];
    int   wpre[14];
    int   kidx[NOUT];
    float red[33];
};

__global__ void __launch_bounds__(NTHR, 1)
k_final(const float* __restrict__ bbox,
        const float* __restrict__ priors,
        float* __restrict__ out) {
    extern __shared__ char smraw[];
    SmemFinal& S = *reinterpret_cast<SmemFinal*>(smraw);
    const int img = blockIdx.x;
    const int tid = threadIdx.x;
    const int lane = tid & 31;
    const int warp = tid >> 5;

    int n = g_cnt[img];
    if (n > SCAP) n = SCAP;
    for (int i = tid; i < n; i += NTHR) S.cand[i] = g_cand[img * SCAP + i];
    int M = 512;
    while (M < n) M <<= 1;
    for (int i = tid; i < M; i += NTHR)
        if (i >= n) S.cand[i] = 0ull;
    __syncthreads();

    // bitonic sort descending on packed (key, ~idx)
    for (int k = 2; k <= M; k <<= 1) {
        for (int j = k >> 1; j > 0; j >>= 1) {
            for (int i = tid; i < M; i += NTHR) {
                int ixj = i ^ j;
                if (ixj > i) {
                    unsigned long long a = S.cand[i], b = S.cand[ixj];
                    bool sw = ((i & k) == 0) ? (a < b) : (a > b);
                    if (sw) { S.cand[i] = b; S.cand[ixj] = a; }
                }
            }
            __syncthreads();
        }
    }

    // top-400 unpack + box decode
    if (tid < NCAND) {
        int r = tid;
        unsigned long long v = S.cand[r];
        float score = unokey((unsigned int)(v >> 32));
        int flat = (int)(~(unsigned int)(v & 0xffffffffu));
        int p = flat / CM1;
        int lbl = flat - p * CM1 + 1;
        const float* loc = bbox + ((size_t)img * NP + p) * 4;
        float px = priors[p * 4 + 0], py = priors[p * 4 + 1];
        float pw = priors[p * 4 + 2], ph = priors[p * 4 + 3];
        float cx = loc[0] * 0.1f * pw + px;
        float cy = loc[1] * 0.1f * ph + py;
        float w = expf(loc[2] * 0.2f) * pw;
        float h = expf(loc[3] * 0.2f) * ph;
        S.bx[r][0] = (cx - w * 0.5f) * 512.0f;
        S.bx[r][1] = (cy - h * 0.5f) * 512.0f;
        S.bx[r][2] = (cx + w * 0.5f) * 512.0f;
        S.bx[r][3] = (cy + h * 0.5f) * 512.0f;
        S.sc[r] = score;
        S.lb[r] = lbl;
    }
    __syncthreads();

    // max over all coords: warp-shfl two-level reduce (2 barriers)
    {
        float mx = -INFINITY;
        for (int i = tid; i < NCAND * 4; i += NTHR) mx = fmaxf(mx, ((float*)S.bx)[i]);
#pragma unroll
        for (int o = 16; o; o >>= 1) mx = fmaxf(mx, __shfl_xor_sync(0xffffffffu, mx, o));
        if (lane == 0) S.red[warp] = mx;
        __syncthreads();
        if (warp == 0) {
            float v = S.red[lane];
#pragma unroll
            for (int o = 16; o; o >>= 1) v = fmaxf(v, __shfl_xor_sync(0xffffffffu, v, o));
            if (lane == 0) S.red[32] = v;
        }
        __syncthreads();
    }
    float maxc = S.red[32];

    // class-offset boxes (SoA float4) + areas on offset boxes
    if (tid < NCAND) {
        int r = tid;
        float off = (float)S.lb[r] * (maxc + 1.0f);
        float x1 = S.bx[r][0] + off, y1 = S.bx[r][1] + off;
        float x2 = S.bx[r][2] + off, y2 = S.bx[r][3] + off;
        S.obx4[r] = make_float4(x1, y1, x2, y2);
        S.area[r] = (x2 - x1) * (y2 - y1);
    }
    __syncthreads();

    // adjacency bitmatrix, only words w >= i>>5 (j < i impossible)
    for (int i = warp; i < NCAND; i += NTHR / 32) {
        float4 bi = S.obx4[i];
        float ai = S.area[i];
        for (int w = i >> 5; w < 13; w++) {
            int j = w * 32 + lane;
            bool pred = false;
            if (j < NCAND && j > i) {
                float4 bj = S.obx4[j];
                float lt0 = fmaxf(bi.x, bj.x);
                float lt1 = fmaxf(bi.y, bj.y);
                float rb0 = fminf(bi.z, bj.z);
                float rb1 = fminf(bi.w, bj.w);
                float ww = fmaxf(rb0 - lt0, 0.0f);
                float hh = fmaxf(rb1 - lt1, 0.0f);
                float inter = ww * hh;
                float uni = ai + S.area[j] - inter;
                pred = (inter / fmaxf(uni, 1e-12f)) > 0.45f;
            }
            unsigned int bits = __ballot_sync(0xffffffffu, pred);
            if (lane == 0) S.adj[i][w] = bits;
        }
    }
    __syncthreads();

    // greedy NMS on warp 0 (13 keep-words, prefetched rows)
    if (tid < 32) {
        unsigned int kw;
        if (lane < 12) kw = 0xffffffffu;
        else if (lane == 12) kw = 0x0000ffffu;
        else kw = 0u;
        unsigned int nextrow = (lane < 13) ? S.adj[0][lane] : 0u;   // (0>>5)==0
        for (int i = 0; i < NCAND; i++) {
            unsigned int row = nextrow;
            nextrow = (lane < 13 && lane >= ((i + 1) >> 5) && i + 1 < NCAND)
                          ? S.adj[i + 1][lane] : 0u;
            unsigned int w = __shfl_sync(0xffffffffu, kw, i >> 5);
            if ((w >> (i & 31)) & 1u) kw &= ~row;
        }
        if (lane < 13) S.keepw[lane] = kw;
    }
    __syncthreads();

    // parallel rank select + output
    if (tid == 0) {
        int sacc = 0;
#pragma unroll
        for (int w = 0; w < 13; w++) { S.wpre[w] = sacc; sacc += __popc(S.keepw[w]); }
        S.wpre[13] = sacc;
    }
    __syncthreads();
    int K = S.wpre[13];
    if (tid < NCAND) {
        int i = tid;
        unsigned int word = S.keepw[i >> 5];
        unsigned int below = word & ((1u << (i & 31)) - 1u);
        int kb = S.wpre[i >> 5] + __popc(below);
        if ((word >> (i & 31)) & 1u) {
            if (kb < NOUT) S.kidx[kb] = i;
        } else {
            int nr2 = i - kb;
            if (K + nr2 < NOUT) S.kidx[K + nr2] = i;
        }
    }
    __syncthreads();

    if (tid < NOUT) {
        int r = tid;
        int i = S.kidx[r];
        bool kept = (S.keepw[i >> 5] >> (i & 31)) & 1u;
        float* ob = out + ((size_t)img * NOUT + r) * 4;
        ob[0] = S.bx[i][0]; ob[1] = S.bx[i][1]; ob[2] = S.bx[i][2]; ob[3] = S.bx[i][3];
        out[NB * NOUT * 4 + img * NOUT + r] = (float)S.lb[i];
        out[NB * NOUT * 5 + img * NOUT + r] = kept ? S.sc[i] : -INFINITY;
    }
}

// ---------------- launch ----------------
extern "C" void kernel_launch(void* const* d_in, const int* in_sizes, int n_in,
                              void* d_out, int out_size) {
    const float* logits = (const float*)d_in[0];
    const float* bbox   = (const float*)d_in[1];
    const float* priors = (const float*)d_in[2];
    float* out = (float*)d_out;

    k_lse_hist<<<dim3(512, 8), 256>>>(logits, 0);
    k_lse_hist<<<dim3(512, 8), 256>>>(logits, 8);
    k_thresh<<<NB, NTHR>>>();
    k_gather<<<dim3(64, NB), 128>>>(logits);
    cudaFuncSetAttribute(k_final, cudaFuncAttributeMaxDynamicSharedMemorySize,
                         (int)sizeof(SmemFinal));
    k_final<<<NB, NTHR, sizeof(SmemFinal)>>>(bbox, priors, out);
}

// round 7
// speedup vs baseline: 1.1844x; 1.1844x over previous
#include <cuda_runtime.h>
#include <math.h>

#define NB    16
#define NP    32768
#define NC    81
#define CM1   80
#define NBINS 2048
#define SCAP  4096
#define RCAP  4096
#define NCAND 400
#define NOUT  100

// ---------------- scratch (static device globals; zero-initialized at load) --------
__device__ float              g_rowsc[NB * NP];
__device__ unsigned int       g_hist[NB * NBINS];   // zeroed in-kernel after use
__device__ int                g_btm[NB];            // row filter bin
__device__ int                g_bte[NB];            // element filter bin
__device__ int                g_cnt[NB];            // reset in-kernel after use
__device__ unsigned int       g_done1[NB];          // K1 block-done counters
__device__ unsigned int       g_done2[NB];          // K2 block-done counters
__device__ unsigned long long g_cand[NB * SCAP];

__device__ __forceinline__ int binf(float s) {
    int b = (int)floorf((s + 30.0f) * (NBINS / 40.0f));
    b = b < 0 ? 0 : b;
    b = b > (NBINS - 1) ? (NBINS - 1) : b;
    return b;
}

__device__ __forceinline__ unsigned int okey(float s) {
    unsigned int u = __float_as_uint(s);
    return (u & 0x80000000u) ? ~u : (u | 0x80000000u);
}
__device__ __forceinline__ float unokey(unsigned int k) {
    return __uint_as_float((k & 0x80000000u) ? (k ^ 0x80000000u) : ~k);
}

// ============ K1: approx row-score + histogram; last block finds threshold ==========
__global__ void __launch_bounds__(256)
k_rowscore(const float* __restrict__ logits) {
    const int img = blockIdx.y;
    const int lane = threadIdx.x & 31;
    const int w = blockIdx.x * 8 + (threadIdx.x >> 5);   // 0..2047 per image
    const float* base = logits + (size_t)img * NP * NC;
    const bool t3 = (lane < 17);

#pragma unroll 1
    for (int it = 0; it < 4; it++) {
        const int p = w * 4 + it * 8192;                 // 4 consecutive rows
        const float* r = base + (size_t)p * NC;
        float a[4], b[4], c[4];
#pragma unroll
        for (int q = 0; q < 4; q++) {                    // 12 loads batched -> MLP
            a[q] = r[q * NC + lane];
            b[q] = r[q * NC + lane + 32];
            c[q] = t3 ? r[q * NC + lane + 64] : -1e30f;
        }
        float rs[4];
#pragma unroll
        for (int q = 0; q < 4; q++) {
            float fa = (lane == 0) ? -1e30f : a[q];      // exclude background (c=0)
            float fg = fmaxf(fmaxf(fa, b[q]), c[q]);
            unsigned int mk = __reduce_max_sync(0xffffffffu, okey(fg));
            float s = __expf(a[q]) + __expf(b[q]) + (t3 ? __expf(c[q]) : 0.0f);
#pragma unroll
            for (int o = 16; o; o >>= 1) s += __shfl_xor_sync(0xffffffffu, s, o);
            rs[q] = unokey(mk) - __logf(s);              // approx row fg score
        }
        if (lane == 0) {
#pragma unroll
            for (int q = 0; q < 4; q++) {
                g_rowsc[img * NP + p + q] = rs[q];
                atomicAdd(&g_hist[img * NBINS + binf(rs[q])], 1u);
            }
        }
    }

    // ---- last-block-per-image: threshold find + hist re-zero ----
    __shared__ int slast;
    __shared__ unsigned int wsum[8];
    __shared__ int sbt;
    __syncthreads();
    __threadfence();
    if (threadIdx.x == 0)
        slast = (atomicAdd(&g_done1[img], 1u) == gridDim.x - 1);
    __syncthreads();
    if (!slast) return;
    __threadfence();

    const int t = threadIdx.x;
    const int warp = t >> 5;
    const int hi = NBINS - 1 - 8 * t;   // 8 descending bins per thread
    unsigned int v[8];
    unsigned int sum = 0;
#pragma unroll
    for (int k = 0; k < 8; k++) {
        v[k] = g_hist[img * NBINS + hi - k];
        g_hist[img * NBINS + hi - k] = 0u;   // re-zero for next replay
        sum += v[k];
    }
    unsigned int x = sum;
#pragma unroll
    for (int o = 1; o < 32; o <<= 1) {
        unsigned int y = __shfl_up_sync(0xffffffffu, x, o);
        if (lane >= o) x += y;
    }
    if (lane == 31) wsum[warp] = x;
    __syncthreads();
    if (warp == 0) {
        unsigned int tv = (lane < 8) ? wsum[lane] : 0u;
        unsigned int tx = tv;
#pragma unroll
        for (int o = 1; o < 8; o <<= 1) {
            unsigned int y = __shfl_up_sync(0xffffffffu, tx, o);
            if (lane >= o) tx += y;
        }
        if (lane < 8) wsum[lane] = tx - tv;   // exclusive warp offsets
    }
    __syncthreads();
    {
        unsigned int incl = x + wsum[warp];
        unsigned int excl = incl - sum;
        if (excl < NCAND && incl >= NCAND) {
            unsigned int cum = excl;
#pragma unroll
            for (int k = 0; k < 8; k++) {
                cum += v[k];
                if (cum >= NCAND) { sbt = hi - k; break; }
            }
        }
        if (t == 255 && incl < NCAND) sbt = 0;   // never expected
    }
    __syncthreads();
    if (t == 0) {
        int bt = sbt;
        int bm = bt - 2; if (bm < 0) bm = 0;   // row margin (approx err << 1 bin)
        int be = bt - 1; if (be < 0) be = 0;   // element margin
        g_btm[img] = bm;
        g_bte[img] = be;
        g_done1[img] = 0u;                     // reset for next replay
    }
}

// ============ K2: gather + exact rescore; last block: sort + NMS + output ==========
struct FinalS {
    unsigned long long cand[SCAP];     // 32 KB
    float4 obx4[NCAND];
    float bx[NCAND][4];
    float sc[NCAND];
    int   lb[NCAND];
    float area[NCAND];
    unsigned int adj[NCAND][13];
    unsigned int keepw[13];
    int   wpre[14];
    int   kidx[NOUT];
    float red[33];
};

__global__ void __launch_bounds__(1024, 1)
k_gather_final(const float* __restrict__ logits,
               const float* __restrict__ bbox,
               const float* __restrict__ priors,
               float* __restrict__ out) {
    extern __shared__ char smraw[];
    FinalS& S = *reinterpret_cast<FinalS*>(smraw);
    int* rows = reinterpret_cast<int*>(smraw);       // overlays S.cand (phase A/B only)
    __shared__ int snr;
    __shared__ int slast;

    const int img = blockIdx.y;
    const int tid = threadIdx.x;
    const int lane = tid & 31;
    const int warp = tid >> 5;
    const int btm = g_btm[img];
    const int bte = g_bte[img];

    if (tid == 0) snr = 0;
    __syncthreads();

    // ---- phase A: scan this block's 4096 rows of approx scores (1 float4/thread) ----
    {
        const float4* rsc4 = (const float4*)(g_rowsc + (size_t)img * NP) + blockIdx.x * 1024;
        float4 v = rsc4[tid];
        int br = blockIdx.x * 4096 + tid * 4;
        if (binf(v.x) >= btm) { int q = atomicAdd(&snr, 1); if (q < RCAP) rows[q] = br; }
        if (binf(v.y) >= btm) { int q = atomicAdd(&snr, 1); if (q < RCAP) rows[q] = br + 1; }
        if (binf(v.z) >= btm) { int q = atomicAdd(&snr, 1); if (q < RCAP) rows[q] = br + 2; }
        if (binf(v.w) >= btm) { int q = atomicAdd(&snr, 1); if (q < RCAP) rows[q] = br + 3; }
    }
    __syncthreads();

    // ---- phase B: exact rescoring (warp per row) -> push candidates to global ----
    {
        int n = snr < RCAP ? snr : RCAP;
        for (int ri = warp; ri < n; ri += 32) {
            int p = rows[ri];
            const float* row = logits + ((size_t)img * NP + p) * NC;
            float a = row[lane];
            float b = row[lane + 32];
            float c = (lane < 17) ? row[lane + 64] : -INFINITY;
            float m = fmaxf(fmaxf(a, b), c);
#pragma unroll
            for (int o = 16; o; o >>= 1) m = fmaxf(m, __shfl_xor_sync(0xffffffffu, m, o));
            float sv = expf(a - m) + expf(b - m);
            if (lane < 17) sv += expf(c - m);
#pragma unroll
            for (int o = 16; o; o >>= 1) sv += __shfl_xor_sync(0xffffffffu, sv, o);
            float logs = logf(sv);
#pragma unroll
            for (int k = 0; k < 3; k++) {
                int cc = lane + 32 * k;
                float xv = (k == 0) ? a : (k == 1) ? b : c;
                if (cc >= 1 && cc < NC) {
                    float scv = (xv - m) - logs;
                    if (binf(scv) >= bte) {
                        int pos = atomicAdd(&g_cnt[img], 1);
                        if (pos < SCAP) {
                            unsigned int flat = (unsigned int)(p * CM1 + (cc - 1));
                            g_cand[img * SCAP + pos] =
                                ((unsigned long long)okey(scv) << 32) | (unsigned int)(~flat);
                        }
                    }
                }
            }
        }
    }

    // ---- handshake: last block of this image proceeds to the finale ----
    __syncthreads();
    __threadfence();
    if (tid == 0)
        slast = (atomicAdd(&g_done2[img], 1u) == gridDim.x - 1);
    __syncthreads();
    if (!slast) return;
    __threadfence();

    // =================== FINALE (runs on 16 blocks, one per image) ===================
    int n = g_cnt[img];
    if (n > SCAP) n = SCAP;
    for (int i = tid; i < n; i += 1024) S.cand[i] = g_cand[img * SCAP + i];
    int M = 512;
    while (M < n) M <<= 1;
    for (int i = tid; i < M; i += 1024)
        if (i >= n) S.cand[i] = 0ull;
    __syncthreads();

    // bitonic sort descending on packed (key, ~idx)
    for (int k = 2; k <= M; k <<= 1) {
        for (int j = k >> 1; j > 0; j >>= 1) {
            for (int i = tid; i < M; i += 1024) {
                int ixj = i ^ j;
                if (ixj > i) {
                    unsigned long long a = S.cand[i], b = S.cand[ixj];
                    bool sw = ((i & k) == 0) ? (a < b) : (a > b);
                    if (sw) { S.cand[i] = b; S.cand[ixj] = a; }
                }
            }
            __syncthreads();
        }
    }

    // top-400 unpack + box decode
    if (tid < NCAND) {
        int r = tid;
        unsigned long long v = S.cand[r];
        float score = unokey((unsigned int)(v >> 32));
        int flat = (int)(~(unsigned int)(v & 0xffffffffu));
        int p = flat / CM1;
        int lbl = flat - p * CM1 + 1;
        const float* loc = bbox + ((size_t)img * NP + p) * 4;
        float px = priors[p * 4 + 0], py = priors[p * 4 + 1];
        float pw = priors[p * 4 + 2], ph = priors[p * 4 + 3];
        float cx = loc[0] * 0.1f * pw + px;
        float cy = loc[1] * 0.1f * ph + py;
        float w = expf(loc[2] * 0.2f) * pw;
        float h = expf(loc[3] * 0.2f) * ph;
        S.bx[r][0] = (cx - w * 0.5f) * 512.0f;
        S.bx[r][1] = (cy - h * 0.5f) * 512.0f;
        S.bx[r][2] = (cx + w * 0.5f) * 512.0f;
        S.bx[r][3] = (cy + h * 0.5f) * 512.0f;
        S.sc[r] = score;
        S.lb[r] = lbl;
    }
    __syncthreads();

    // max over all coords: two-level warp reduce
    {
        float mx = -INFINITY;
        for (int i = tid; i < NCAND * 4; i += 1024) mx = fmaxf(mx, ((float*)S.bx)[i]);
#pragma unroll
        for (int o = 16; o; o >>= 1) mx = fmaxf(mx, __shfl_xor_sync(0xffffffffu, mx, o));
        if (lane == 0) S.red[warp] = mx;
        __syncthreads();
        if (warp == 0) {
            float v = S.red[lane];
#pragma unroll
            for (int o = 16; o; o >>= 1) v = fmaxf(v, __shfl_xor_sync(0xffffffffu, v, o));
            if (lane == 0) S.red[32] = v;
        }
        __syncthreads();
    }
    float maxc = S.red[32];

    // class-offset boxes + areas (on offset boxes, matching reference rounding)
    if (tid < NCAND) {
        int r = tid;
        float off = (float)S.lb[r] * (maxc + 1.0f);
        float x1 = S.bx[r][0] + off, y1 = S.bx[r][1] + off;
        float x2 = S.bx[r][2] + off, y2 = S.bx[r][3] + off;
        S.obx4[r] = make_float4(x1, y1, x2, y2);
        S.area[r] = (x2 - x1) * (y2 - y1);
    }
    __syncthreads();

    // adjacency bitmatrix, words w >= i>>5 only
    for (int i = warp; i < NCAND; i += 32) {
        float4 bi = S.obx4[i];
        float ai = S.area[i];
        for (int w = i >> 5; w < 13; w++) {
            int j = w * 32 + lane;
            bool pred = false;
            if (j < NCAND && j > i) {
                float4 bj = S.obx4[j];
                float lt0 = fmaxf(bi.x, bj.x);
                float lt1 = fmaxf(bi.y, bj.y);
                float rb0 = fminf(bi.z, bj.z);
                float rb1 = fminf(bi.w, bj.w);
                float ww = fmaxf(rb0 - lt0, 0.0f);
                float hh = fmaxf(rb1 - lt1, 0.0f);
                float inter = ww * hh;
                float uni = ai + S.area[j] - inter;
                pred = (inter / fmaxf(uni, 1e-12f)) > 0.45f;
            }
            unsigned int bits = __ballot_sync(0xffffffffu, pred);
            if (lane == 0) S.adj[i][w] = bits;
        }
    }
    __syncthreads();

    // greedy NMS on warp 0 (13 keep-words, prefetched rows)
    if (tid < 32) {
        unsigned int kw;
        if (lane < 12) kw = 0xffffffffu;
        else if (lane == 12) kw = 0x0000ffffu;
        else kw = 0u;
        unsigned int nextrow = (lane < 13) ? S.adj[0][lane] : 0u;
        for (int i = 0; i < NCAND; i++) {
            unsigned int row = nextrow;
            nextrow = (lane < 13 && lane >= ((i + 1) >> 5) && i + 1 < NCAND)
                          ? S.adj[i + 1][lane] : 0u;
            unsigned int w = __shfl_sync(0xffffffffu, kw, i >> 5);
            if ((w >> (i & 31)) & 1u) kw &= ~row;
        }
        if (lane < 13) S.keepw[lane] = kw;
    }
    __syncthreads();

    // parallel rank select + output
    if (tid == 0) {
        int sacc = 0;
#pragma unroll
        for (int w = 0; w < 13; w++) { S.wpre[w] = sacc; sacc += __popc(S.keepw[w]); }
        S.wpre[13] = sacc;
    }
    __syncthreads();
    int K = S.wpre[13];
    if (tid < NCAND) {
        int i = tid;
        unsigned int word = S.keepw[i >> 5];
        unsigned int below = word & ((1u << (i & 31)) - 1u);
        int kb = S.wpre[i >> 5] + __popc(below);
        if ((word >> (i & 31)) & 1u) {
            if (kb < NOUT) S.kidx[kb] = i;
        } else {
            int nr2 = i - kb;
            if (K + nr2 < NOUT) S.kidx[K + nr2] = i;
        }
    }
    __syncthreads();

    if (tid < NOUT) {
        int r = tid;
        int i = S.kidx[r];
        bool kept = (S.keepw[i >> 5] >> (i & 31)) & 1u;
        float* ob = out + ((size_t)img * NOUT + r) * 4;
        ob[0] = S.bx[i][0]; ob[1] = S.bx[i][1]; ob[2] = S.bx[i][2]; ob[3] = S.bx[i][3];
        out[NB * NOUT * 4 + img * NOUT + r] = (float)S.lb[i];
        out[NB * NOUT * 5 + img * NOUT + r] = kept ? S.sc[i] : -INFINITY;
    }
    if (tid == 0) {                        // reset for next graph replay
        g_cnt[img] = 0;
        g_done2[img] = 0u;
    }
}

// ---------------- launch ----------------
extern "C" void kernel_launch(void* const* d_in, const int* in_sizes, int n_in,
                              void* d_out, int out_size) {
    const float* logits = (const float*)d_in[0];
    const float* bbox   = (const float*)d_in[1];
    const float* priors = (const float*)d_in[2];
    float* out = (float*)d_out;

    k_rowscore<<<dim3(256, NB), 256>>>(logits);
    cudaFuncSetAttribute(k_gather_final, cudaFuncAttributeMaxDynamicSharedMemorySize,
                         (int)sizeof(FinalS));
    k_gather_final<<<dim3(8, NB), 1024, sizeof(FinalS)>>>(logits, bbox, priors, out);
}